// round 8
// baseline (speedup 1.0000x reference)
#include <cuda_runtime.h>
#include <cuda_fp16.h>
#include <cstdint>

// ---------------------------------------------------------------------------
// involution_81106162418291 — fp16 1-pass, swapped-role mma (D[px,k]),
// persistent w2 fragments, fused w2 conversion, 2 syncs/chunk.
// B=4, C=256, H=W=56, GC=4 -> G=64, K=7 -> K2=49, Cr=64, stride=1, pad=3
// ---------------------------------------------------------------------------

#define Bsz 4
#define C    256
#define Cr   64
#define HW   3136
#define Hdim 56
#define G    64
#define K2   49

__device__ __half g_yh[Bsz * HW * Cr];     // y fp16, [b][hw][cr]

__device__ __forceinline__ uint32_t smem_u32(const void* p) {
    uint32_t a;
    asm("{ .reg .u64 t; cvta.to.shared.u64 t, %1; cvt.u32.u64 %0, t; }"
        : "=r"(a) : "l"(p));
    return a;
}

#define LDSM_X4(r0,r1,r2,r3,addr) \
    asm volatile("ldmatrix.sync.aligned.m8n8.x4.shared.b16 {%0,%1,%2,%3}, [%4];" \
        : "=r"(r0),"=r"(r1),"=r"(r2),"=r"(r3) : "r"(addr))
#define LDSM_X2(r0,r1,addr) \
    asm volatile("ldmatrix.sync.aligned.m8n8.x2.shared.b16 {%0,%1}, [%2];" \
        : "=r"(r0),"=r"(r1) : "r"(addr))
#define MMA16816(c,a,b) \
    asm volatile("mma.sync.aligned.m16n8k16.row.col.f32.f16.f16.f32 " \
        "{%0,%1,%2,%3}, {%4,%5,%6,%7}, {%8,%9}, {%0,%1,%2,%3};" \
        : "+f"((c)[0]),"+f"((c)[1]),"+f"((c)[2]),"+f"((c)[3]) \
        : "r"((a)[0]),"r"((a)[1]),"r"((a)[2]),"r"((a)[3]), "r"((b)[0]),"r"((b)[1]))
#define CP_ASYNC16(dst, src) \
    asm volatile("cp.async.cg.shared.global [%0], [%1], 16;" :: "r"(dst), "l"(src))
#define CP_COMMIT() asm volatile("cp.async.commit_group;")
#define CP_WAIT(n)  asm volatile("cp.async.wait_group %0;" :: "n"(n))

// ---------------------------------------------------------------------------
// k1: y = relu(bn(conv1(x))) -> fp16 at [b][hw][cr]. grid (49, 4), 16 cr/blk.
// ---------------------------------------------------------------------------
__global__ void __launch_bounds__(256) k1_conv_bn_relu(
    const float* __restrict__ x,  const float* __restrict__ w1,
    const float* __restrict__ b1, const float* __restrict__ gamma,
    const float* __restrict__ beta, const float* __restrict__ mean,
    const float* __restrict__ var)
{
    __shared__ float w1s[16 * 260];          // [cr][c], pitch 260
    const int tid = threadIdx.x;
    const int cr0 = blockIdx.y * 16;

    for (int idx = tid; idx < 16 * C; idx += 256) {
        int i = idx >> 8;
        int c = idx & 255;
        w1s[i * 260 + c] = w1[(cr0 + i) * C + c];
    }
    __syncthreads();

    const int p  = blockIdx.x * 256 + tid;
    const int b  = p / HW;
    const int hw = p - b * HW;
    const float* xb = x + (size_t)b * C * HW + hw;

    float acc[16];
#pragma unroll
    for (int i = 0; i < 16; i++) acc[i] = 0.f;

    for (int c = 0; c < C; c += 4) {
        float xv0 = xb[c * HW];
        float xv1 = xb[(c + 1) * HW];
        float xv2 = xb[(c + 2) * HW];
        float xv3 = xb[(c + 3) * HW];
#pragma unroll
        for (int i = 0; i < 16; i++) {
            float4 w = *(const float4*)&w1s[i * 260 + c];
            acc[i] += w.x * xv0 + w.y * xv1 + w.z * xv2 + w.w * xv3;
        }
    }

#pragma unroll
    for (int i = 0; i < 16; i++) {
        int cr = cr0 + i;
        float inv   = gamma[cr] * rsqrtf(var[cr] + 1e-5f);
        float shift = beta[cr] - mean[cr] * inv;
        float v = fmaxf((acc[i] + b1[cr]) * inv + shift, 0.f);
        g_yh[(size_t)(b * HW + hw) * Cr + cr] = __float2half(v);
    }
}

// ---------------------------------------------------------------------------
// k2: block = (row strip, batch, group). grid (7, 4, 64), 128 thr, 3 CTAs/SM.
//   w2 converted fp32->fp16 into smem once, ldsm'd to persistent B frags.
//   Per chunk: cp.async y tile (single fp16 buf, double-buffered),
//   A = y frags (4 ldsm), 28 MMA (D[px,k]), epilogue, involution.
// smem (57472B): A(w2)@0 9216 | B(y)@9216 2x9216 | wts@27648 [49..56][68]f32
//                | xs@41088 4x14x72 f32 | b2s@57216
// ---------------------------------------------------------------------------
#define S_A   0u
#define S_B   9216u
#define S_WTS 27648u
#define S_XS  41088u
#define S_B2  57216u
#define SMEM_K2 57472

__global__ void __launch_bounds__(128, 3) k2_involution(
    const float* __restrict__ x,  const float* __restrict__ w2,
    const float* __restrict__ b2, float* __restrict__ out)
{
    extern __shared__ __align__(16) char buf[];
    const uint32_t sb = smem_u32(buf);
    const int tid = threadIdx.x, wid = tid >> 5, lane = tid & 31;
    const int b  = blockIdx.y;
    const int g  = blockIdx.z;
    const int h0 = blockIdx.x * 8;

    float* wts = (float*)(buf + S_WTS);
    float* xs  = (float*)(buf + S_XS);
    float* b2s = (float*)(buf + S_B2);

    // ---- stage A: convert w2 fp32 -> fp16 rows (49 x 64, pitch 144B) ----
    for (int idx = tid; idx < K2 * 8; idx += 128) {
        int r = idx >> 3, j = idx & 7;
        const float4* src = (const float4*)(w2 + (size_t)(g * K2 + r) * Cr + j * 8);
        float4 v0 = src[0], v1 = src[1];
        __half2 h0h = __floats2half2_rn(v0.x, v0.y);
        __half2 h1h = __floats2half2_rn(v0.z, v0.w);
        __half2 h2h = __floats2half2_rn(v1.x, v1.y);
        __half2 h3h = __floats2half2_rn(v1.z, v1.w);
        uint4 pk;
        pk.x = *(uint32_t*)&h0h; pk.y = *(uint32_t*)&h1h;
        pk.z = *(uint32_t*)&h2h; pk.w = *(uint32_t*)&h3h;
        *(uint4*)(buf + S_A + (uint32_t)(r * 144 + j * 16)) = pk;
    }
    // zero-pad rows 49..63 (ldsm touches rows up to 55; keep clean)
    for (int idx = tid; idx < 15 * 9; idx += 128) {
        int r = 49 + idx / 9, j = idx % 9;
        *(uint4*)(buf + S_A + (uint32_t)(r * 144 + j * 16)) = make_uint4(0, 0, 0, 0);
    }
    if (tid < K2) b2s[tid] = b2[g * K2 + tid];
    // ---- stage x halo strip: 4 ch x 14 rows x 62 cols (pitch 72) ----
    for (int idx = tid; idx < 4 * 14 * 62; idx += 128) {
        int ch = idx / 868, rem = idx - ch * 868;
        int r = rem / 62, col = rem - r * 62;
        int hh = h0 + r - 3, ww = col - 3;
        float v = 0.f;
        if (hh >= 0 && hh < Hdim && ww >= 0 && ww < Hdim)
            v = x[((size_t)(b * C + g * 4 + ch) * Hdim + hh) * Hdim + ww];
        xs[(ch * 14 + r) * 72 + col] = v;
    }

    // ---- cp.async y stager: 64 px rows x 8 x 16B = 512 ops ----
    const char* yhp = (const char*)g_yh;
    auto stage_B = [&](int tw, int q) {
#pragma unroll
        for (int it = 0; it < 4; it++) {
            int idx = it * 128 + tid;
            int n = idx >> 3, j = idx & 7;
            int hw = (h0 + (n >> 3)) * Hdim + tw * 8 + (n & 7);
            uint32_t dst = sb + S_B + (uint32_t)(q * 9216 + n * 144 + j * 16);
            CP_ASYNC16(dst, yhp + (size_t)(b * HW + hw) * 128 + j * 16);
        }
    };

    stage_B(0, 0);
    CP_COMMIT();
    __syncthreads();   // A(w2), xs, b2s visible

    // ---- persistent w2 fragments: bw[nt][kk][2] (n8k16) ----
    uint32_t bw[7][4][2];
    const uint32_t bbase = sb + S_A
        + ((uint32_t)(lane & 7) * 144 + (uint32_t)((lane >> 3) & 1) * 16);
#pragma unroll
    for (int nt = 0; nt < 7; nt++)
#pragma unroll
        for (int kk = 0; kk < 4; kk++)
            LDSM_X2(bw[nt][kk][0], bw[nt][kk][1],
                    bbase + (uint32_t)(nt * 8 * 144 + kk * 32));

    const uint32_t abase0 = ((uint32_t)(wid * 16 + (lane & 15)) * 144
                           + (uint32_t)(lane >> 4) * 16);

    // involution mapping: thread = (px, ch-pair)
    const int pixi = tid & 63;
    const int cp   = tid >> 6;
    const int phi  = pixi >> 3, pwi = pixi & 7;
    const float* xr0 = xs + ((cp)     * 14 + phi) * 72 + pwi;
    const float* xr1 = xs + ((cp + 2) * 14 + phi) * 72 + pwi;

    const int px0  = wid * 16 + (lane >> 2);
    const int kcol = (lane & 3) * 2;

    for (int tw = 0; tw < 7; tw++) {
        const int q  = tw & 1;
        const int w0 = tw * 8;

        CP_WAIT(0);
        __syncthreads();   // B(tw) ready; involution(tw-1) done (wts writable)

        // ---- A = y frags for this chunk ----
        uint32_t av[4][4];
        const uint32_t ab = sb + S_B + (uint32_t)(q * 9216) + abase0;
#pragma unroll
        for (int kk = 0; kk < 4; kk++)
            LDSM_X4(av[kk][0], av[kk][1], av[kk][2], av[kk][3],
                    ab + (uint32_t)(kk * 32));

        if (tw < 6) { stage_B(tw + 1, q ^ 1); CP_COMMIT(); }

        // ---- 28 MMA: D[16px x 56k] per warp ----
        float c[7][4];
#pragma unroll
        for (int nt = 0; nt < 7; nt++)
#pragma unroll
            for (int i = 0; i < 4; i++) c[nt][i] = 0.f;
#pragma unroll
        for (int kk = 0; kk < 4; kk++)
#pragma unroll
            for (int nt = 0; nt < 7; nt++)
                MMA16816(c[nt], av[kk], bw[nt][kk]);

        // ---- epilogue: D(px,k) -> wts[k][px] (+bias), pitch 68 ----
#pragma unroll
        for (int nt = 0; nt < 7; nt++) {
            int k0 = nt * 8 + kcol;
            if (k0 < K2) {
                float bb = b2s[k0];
                wts[k0 * 68 + px0]     = c[nt][0] + bb;
                wts[k0 * 68 + px0 + 8] = c[nt][2] + bb;
            }
            if (k0 + 1 < K2) {
                float bb = b2s[k0 + 1];
                wts[(k0 + 1) * 68 + px0]     = c[nt][1] + bb;
                wts[(k0 + 1) * 68 + px0 + 8] = c[nt][3] + bb;
            }
        }
        __syncthreads();

        // ---- involution: one wts load feeds 2 channels ----
        const float* xb0 = xr0 + w0;
        const float* xb1 = xr1 + w0;
        float s0 = 0.f, s1 = 0.f;
#pragma unroll
        for (int ky = 0; ky < 7; ky++) {
#pragma unroll
            for (int kx = 0; kx < 7; kx++) {
                float wk = wts[(ky * 7 + kx) * 68 + pixi];
                s0 += wk * xb0[ky * 72 + kx];
                s1 += wk * xb1[ky * 72 + kx];
            }
        }
        size_t o0 = ((size_t)(b * C + g * 4 + cp)     * Hdim + h0 + phi) * Hdim + w0 + pwi;
        size_t o1 = ((size_t)(b * C + g * 4 + cp + 2) * Hdim + h0 + phi) * Hdim + w0 + pwi;
        out[o0] = s0;
        out[o1] = s1;
    }
}

extern "C" void kernel_launch(void* const* d_in, const int* in_sizes, int n_in,
                              void* d_out, int out_size)
{
    const float* x     = (const float*)d_in[0];
    const float* w1    = (const float*)d_in[1];
    const float* b1    = (const float*)d_in[2];
    const float* gamma = (const float*)d_in[3];
    const float* beta  = (const float*)d_in[4];
    const float* mean  = (const float*)d_in[5];
    const float* var   = (const float*)d_in[6];
    const float* w2    = (const float*)d_in[7];
    const float* b2    = (const float*)d_in[8];
    float* out = (float*)d_out;

    cudaFuncSetAttribute(k2_involution,
                         cudaFuncAttributeMaxDynamicSharedMemorySize, SMEM_K2);

    dim3 g1(49, 4);
    k1_conv_bn_relu<<<g1, 256>>>(x, w1, b1, gamma, beta, mean, var);

    dim3 g2(7, 4, 64);
    k2_involution<<<g2, 128, SMEM_K2>>>(x, w2, b2, out);
}

// round 9
// speedup vs baseline: 1.5989x; 1.5989x over previous
#include <cuda_runtime.h>
#include <cuda_fp16.h>
#include <cstdint>

// ---------------------------------------------------------------------------
// involution_81106162418291 — R7 structure, single-pass fp16, fused w2 convert
// B=4, C=256, H=W=56, GC=4 -> G=64, K=7 -> K2=49, Cr=64, stride=1, pad=3
// ---------------------------------------------------------------------------

#define Bsz 4
#define C    256
#define Cr   64
#define HW   3136
#define Hdim 56
#define G    64
#define K2   49

__device__ __half g_yh[Bsz * HW * Cr];     // y fp16, [b][hw][cr]

__device__ __forceinline__ uint32_t smem_u32(const void* p) {
    uint32_t a;
    asm("{ .reg .u64 t; cvta.to.shared.u64 t, %1; cvt.u32.u64 %0, t; }"
        : "=r"(a) : "l"(p));
    return a;
}

#define LDSM_X4(r0,r1,r2,r3,addr) \
    asm volatile("ldmatrix.sync.aligned.m8n8.x4.shared.b16 {%0,%1,%2,%3}, [%4];" \
        : "=r"(r0),"=r"(r1),"=r"(r2),"=r"(r3) : "r"(addr))
#define LDSM_X2(r0,r1,addr) \
    asm volatile("ldmatrix.sync.aligned.m8n8.x2.shared.b16 {%0,%1}, [%2];" \
        : "=r"(r0),"=r"(r1) : "r"(addr))
#define MMA16816(c,a,b) \
    asm volatile("mma.sync.aligned.m16n8k16.row.col.f32.f16.f16.f32 " \
        "{%0,%1,%2,%3}, {%4,%5,%6,%7}, {%8,%9}, {%0,%1,%2,%3};" \
        : "+f"((c)[0]),"+f"((c)[1]),"+f"((c)[2]),"+f"((c)[3]) \
        : "r"((a)[0]),"r"((a)[1]),"r"((a)[2]),"r"((a)[3]), "r"((b)[0]),"r"((b)[1]))
#define CP_ASYNC16(dst, src) \
    asm volatile("cp.async.cg.shared.global [%0], [%1], 16;" :: "r"(dst), "l"(src))
#define CP_COMMIT() asm volatile("cp.async.commit_group;")
#define CP_WAIT(n)  asm volatile("cp.async.wait_group %0;" :: "n"(n))

// ---------------------------------------------------------------------------
// k1: y = relu(bn(conv1(x))) -> fp16 [b][hw][cr]. grid (49, 4), 16 cr/block.
// Vectorized 2x uint4 stores (16 consecutive cr halves per thread).
// ---------------------------------------------------------------------------
__global__ void __launch_bounds__(256) k1_conv_bn_relu(
    const float* __restrict__ x,  const float* __restrict__ w1,
    const float* __restrict__ b1, const float* __restrict__ gamma,
    const float* __restrict__ beta, const float* __restrict__ mean,
    const float* __restrict__ var)
{
    __shared__ float w1s[16 * 260];          // [cr][c], pitch 260
    const int tid = threadIdx.x;
    const int cr0 = blockIdx.y * 16;

    for (int idx = tid; idx < 16 * C; idx += 256) {
        int i = idx >> 8;
        int c = idx & 255;
        w1s[i * 260 + c] = w1[(cr0 + i) * C + c];
    }
    __syncthreads();

    const int p  = blockIdx.x * 256 + tid;
    const int b  = p / HW;
    const int hw = p - b * HW;
    const float* xb = x + (size_t)b * C * HW + hw;

    float acc[16];
#pragma unroll
    for (int i = 0; i < 16; i++) acc[i] = 0.f;

    for (int c = 0; c < C; c += 4) {
        float xv0 = xb[c * HW];
        float xv1 = xb[(c + 1) * HW];
        float xv2 = xb[(c + 2) * HW];
        float xv3 = xb[(c + 3) * HW];
#pragma unroll
        for (int i = 0; i < 16; i++) {
            float4 w = *(const float4*)&w1s[i * 260 + c];
            acc[i] += w.x * xv0 + w.y * xv1 + w.z * xv2 + w.w * xv3;
        }
    }

    uint32_t pk[8];
#pragma unroll
    for (int i = 0; i < 16; i++) {
        int cr = cr0 + i;
        float inv   = gamma[cr] * rsqrtf(var[cr] + 1e-5f);
        float shift = beta[cr] - mean[cr] * inv;
        acc[i] = fmaxf((acc[i] + b1[cr]) * inv + shift, 0.f);
    }
#pragma unroll
    for (int i = 0; i < 8; i++) {
        __half2 h = __floats2half2_rn(acc[2 * i], acc[2 * i + 1]);
        pk[i] = *(uint32_t*)&h;
    }
    uint4* dst = (uint4*)(g_yh + (size_t)(b * HW + hw) * Cr + cr0);
    dst[0] = make_uint4(pk[0], pk[1], pk[2], pk[3]);
    dst[1] = make_uint4(pk[4], pk[5], pk[6], pk[7]);
}

// ---------------------------------------------------------------------------
// k2: block = (row strip, batch, group). grid (7, 4, 64), 128 thr, 3 CTAs/SM.
//   A (w2 fp16, converted in-kernel) in regs once (4 m-tiles/warp);
//   per chunk: cp.async double-buffered y tile, single-pass MMA (32/warp),
//   epilogue, involution with thread=(px, ch-pair).
// smem (54784B): A@0 7168 | B@7168 2x9216 | wts@25600 [49][65]f32 12800 |
//                xs@38400 4x14x72 f32 16128 | b2s@54528 196
// ---------------------------------------------------------------------------
#define S_A   0u
#define S_B   7168u
#define S_WTS 25600u
#define S_XS  38400u
#define S_B2  54528u
#define SMEM_K2 54784

__global__ void __launch_bounds__(128, 3) k2_involution(
    const float* __restrict__ x,  const float* __restrict__ w2,
    const float* __restrict__ b2, float* __restrict__ out)
{
    extern __shared__ __align__(16) char buf[];
    const uint32_t sb = smem_u32(buf);
    const int tid = threadIdx.x, wid = tid >> 5, lane = tid & 31;
    const int nq = wid;                  // warp owns px [16nq, 16nq+16)
    const int b  = blockIdx.y;
    const int g  = blockIdx.z;
    const int h0 = blockIdx.x * 8;

    float* wts = (float*)(buf + S_WTS);
    float* xs  = (float*)(buf + S_XS);
    float* b2s = (float*)(buf + S_B2);

    // ---- stage A: convert w2 fp32 -> fp16 (49 rows x 64, pitch 144B) ----
    for (int idx = tid; idx < K2 * 8; idx += 128) {
        int r = idx >> 3, j = idx & 7;
        const float4* src = (const float4*)(w2 + (size_t)(g * K2 + r) * Cr + j * 8);
        float4 v0 = src[0], v1 = src[1];
        __half2 h0h = __floats2half2_rn(v0.x, v0.y);
        __half2 h1h = __floats2half2_rn(v0.z, v0.w);
        __half2 h2h = __floats2half2_rn(v1.x, v1.y);
        __half2 h3h = __floats2half2_rn(v1.z, v1.w);
        uint4 pk;
        pk.x = *(uint32_t*)&h0h; pk.y = *(uint32_t*)&h1h;
        pk.z = *(uint32_t*)&h2h; pk.w = *(uint32_t*)&h3h;
        *(uint4*)(buf + S_A + (uint32_t)(r * 144 + j * 16)) = pk;
    }
    // zero-pad rows 49..63 (ldmatrix reads m-tiles up to row 63)
    for (int idx = tid; idx < 15 * 9; idx += 128) {
        int r = 49 + idx / 9, j = idx % 9;
        *(uint4*)(buf + S_A + (uint32_t)(r * 144 + j * 16)) = make_uint4(0, 0, 0, 0);
    }
    if (tid < K2) b2s[tid] = b2[g * K2 + tid];
    // ---- stage x halo strip: 4 ch x 14 rows x 62 cols (pitch 72) ----
    for (int idx = tid; idx < 4 * 14 * 62; idx += 128) {
        int ch = idx / 868, rem = idx - ch * 868;
        int r = rem / 62, col = rem - r * 62;
        int hh = h0 + r - 3, ww = col - 3;
        float v = 0.f;
        if (hh >= 0 && hh < Hdim && ww >= 0 && ww < Hdim)
            v = x[((size_t)(b * C + g * 4 + ch) * Hdim + hh) * Hdim + ww];
        xs[(ch * 14 + r) * 72 + col] = v;
    }

    // ---- cp.async y stager: 64 px rows x 8 x 16B = 512 ops ----
    const char* yhp = (const char*)g_yh;
    auto stage_B = [&](int tw, int q) {
#pragma unroll
        for (int it = 0; it < 4; it++) {
            int idx = it * 128 + tid;
            int n = idx >> 3, j = idx & 7;
            int hw = (h0 + (n >> 3)) * Hdim + tw * 8 + (n & 7);
            uint32_t dst = sb + S_B + (uint32_t)(q * 9216 + n * 144 + j * 16);
            CP_ASYNC16(dst, yhp + (size_t)(b * HW + hw) * 128 + j * 16);
        }
    };

    stage_B(0, 0);
    CP_COMMIT();
    __syncthreads();    // A + xs + b2s visible

    // ---- ldmatrix A fragments into registers (4 m-tiles, persist) ----
    uint32_t ah[4][4][4];
    const uint32_t aoff = ((uint32_t)(lane & 15) * 72 + (uint32_t)(lane >> 4) * 8) * 2;
#pragma unroll
    for (int mt = 0; mt < 4; mt++) {
        uint32_t rowb = (uint32_t)(mt * 16 * 144);
#pragma unroll
        for (int kk = 0; kk < 4; kk++)
            LDSM_X4(ah[mt][kk][0], ah[mt][kk][1], ah[mt][kk][2], ah[mt][kk][3],
                    sb + S_A + aoff + rowb + (uint32_t)(kk * 32));
    }

    const uint32_t boff = ((uint32_t)(nq * 16 + (lane & 7)) * 72
                         + (uint32_t)((lane >> 3) & 1) * 8) * 2;

    // involution mapping: thread = (pixel, ch-pair)
    const int pixi = tid & 63;
    const int cp   = tid >> 6;                 // 0..1 -> channels cp, cp+2
    const int phi  = pixi >> 3, pwi = pixi & 7;
    const float* xr0 = xs + ((cp)     * 14 + phi) * 72 + pwi;
    const float* xr1 = xs + ((cp + 2) * 14 + phi) * 72 + pwi;

    for (int tw = 0; tw < 7; tw++) {
        const int q  = tw & 1;
        const int w0 = tw * 8;

        if (tw < 6) {
            stage_B(tw + 1, q ^ 1);
            CP_COMMIT();
            CP_WAIT(1);
        } else {
            CP_WAIT(0);
        }
        __syncthreads();   // B(tw) visible; involution(tw-1) done (wts writable)

        // ---- GEMM: single-pass fp16, A in registers ----
        const uint32_t bhi = sb + S_B + (uint32_t)(q * 9216);
        float c[4][2][4];
#pragma unroll
        for (int mt = 0; mt < 4; mt++)
#pragma unroll
            for (int nt = 0; nt < 2; nt++)
#pragma unroll
                for (int i = 0; i < 4; i++) c[mt][nt][i] = 0.f;

#pragma unroll
        for (int kk = 0; kk < 4; kk++) {
            uint32_t bh[2][2];
#pragma unroll
            for (int nt = 0; nt < 2; nt++) {
                uint32_t o = boff + (uint32_t)(nt * 8 * 144 + kk * 32);
                LDSM_X2(bh[nt][0], bh[nt][1], bhi + o);
            }
#pragma unroll
            for (int mt = 0; mt < 4; mt++)
#pragma unroll
                for (int nt = 0; nt < 2; nt++)
                    MMA16816(c[mt][nt], ah[mt][kk], bh[nt]);
        }
        __syncthreads();   // GEMM ldsm done; involution(tw-1) done

        // ---- epilogue: fragments -> wts (+bias) ----
#pragma unroll
        for (int mt = 0; mt < 4; mt++) {
            int r0 = mt * 16 + (lane >> 2);
            int r1 = r0 + 8;
#pragma unroll
            for (int nt = 0; nt < 2; nt++) {
                int col = nq * 16 + nt * 8 + (lane & 3) * 2;
                if (r0 < K2) {
                    float bias = b2s[r0];
                    wts[r0 * 65 + col]     = c[mt][nt][0] + bias;
                    wts[r0 * 65 + col + 1] = c[mt][nt][1] + bias;
                }
                if (r1 < K2) {
                    float bias = b2s[r1];
                    wts[r1 * 65 + col]     = c[mt][nt][2] + bias;
                    wts[r1 * 65 + col + 1] = c[mt][nt][3] + bias;
                }
            }
        }
        __syncthreads();

        // ---- involution: one wts load feeds 2 channels ----
        const float* xb0 = xr0 + w0;
        const float* xb1 = xr1 + w0;
        float s0 = 0.f, s1 = 0.f;
#pragma unroll
        for (int ky = 0; ky < 7; ky++) {
#pragma unroll
            for (int kx = 0; kx < 7; kx++) {
                float wk = wts[(ky * 7 + kx) * 65 + pixi];
                s0 += wk * xb0[ky * 72 + kx];
                s1 += wk * xb1[ky * 72 + kx];
            }
        }
        size_t o0 = ((size_t)(b * C + g * 4 + cp)     * Hdim + h0 + phi) * Hdim + w0 + pwi;
        size_t o1 = ((size_t)(b * C + g * 4 + cp + 2) * Hdim + h0 + phi) * Hdim + w0 + pwi;
        out[o0] = s0;
        out[o1] = s1;
    }
}

extern "C" void kernel_launch(void* const* d_in, const int* in_sizes, int n_in,
                              void* d_out, int out_size)
{
    const float* x     = (const float*)d_in[0];
    const float* w1    = (const float*)d_in[1];
    const float* b1    = (const float*)d_in[2];
    const float* gamma = (const float*)d_in[3];
    const float* beta  = (const float*)d_in[4];
    const float* mean  = (const float*)d_in[5];
    const float* var   = (const float*)d_in[6];
    const float* w2    = (const float*)d_in[7];
    const float* b2    = (const float*)d_in[8];
    float* out = (float*)d_out;

    cudaFuncSetAttribute(k2_involution,
                         cudaFuncAttributeMaxDynamicSharedMemorySize, SMEM_K2);

    dim3 g1(49, 4);
    k1_conv_bn_relu<<<g1, 256>>>(x, w1, b1, gamma, beta, mean, var);

    dim3 g2(7, 4, 64);
    k2_involution<<<g2, 128, SMEM_K2>>>(x, w2, b2, out);
}

// round 11
// speedup vs baseline: 1.9211x; 1.2015x over previous
#include <cuda_runtime.h>
#include <cuda_fp16.h>
#include <cstdint>

// ---------------------------------------------------------------------------
// involution_81106162418291 — fp16 single-pass MMA; fp16 wts+xs involution
// with px-pairing; wts double-buffered (2 syncs/chunk); 4 CTAs/SM.
// B=4, C=256, H=W=56, GC=4 -> G=64, K=7 -> K2=49, Cr=64, stride=1, pad=3
// ---------------------------------------------------------------------------

#define Bsz 4
#define C    256
#define Cr   64
#define HW   3136
#define Hdim 56
#define G    64
#define K2   49

__device__ __half g_yh[Bsz * HW * Cr];     // y fp16, [b][hw][cr]

__device__ __forceinline__ uint32_t smem_u32(const void* p) {
    uint32_t a;
    asm("{ .reg .u64 t; cvta.to.shared.u64 t, %1; cvt.u32.u64 %0, t; }"
        : "=r"(a) : "l"(p));
    return a;
}

#define LDSM_X4(r0,r1,r2,r3,addr) \
    asm volatile("ldmatrix.sync.aligned.m8n8.x4.shared.b16 {%0,%1,%2,%3}, [%4];" \
        : "=r"(r0),"=r"(r1),"=r"(r2),"=r"(r3) : "r"(addr))
#define LDSM_X2(r0,r1,addr) \
    asm volatile("ldmatrix.sync.aligned.m8n8.x2.shared.b16 {%0,%1}, [%2];" \
        : "=r"(r0),"=r"(r1) : "r"(addr))
#define MMA16816(c,a,b) \
    asm volatile("mma.sync.aligned.m16n8k16.row.col.f32.f16.f16.f32 " \
        "{%0,%1,%2,%3}, {%4,%5,%6,%7}, {%8,%9}, {%0,%1,%2,%3};" \
        : "+f"((c)[0]),"+f"((c)[1]),"+f"((c)[2]),"+f"((c)[3]) \
        : "r"((a)[0]),"r"((a)[1]),"r"((a)[2]),"r"((a)[3]), "r"((b)[0]),"r"((b)[1]))
#define CP_ASYNC16(dst, src) \
    asm volatile("cp.async.cg.shared.global [%0], [%1], 16;" :: "r"(dst), "l"(src))
#define CP_COMMIT() asm volatile("cp.async.commit_group;")
#define CP_WAIT(n)  asm volatile("cp.async.wait_group %0;" :: "n"(n))

// ---------------------------------------------------------------------------
// k1: y = relu(bn(conv1(x))) -> fp16 [b][hw][cr]. grid (98, 4), 128 thr.
// ---------------------------------------------------------------------------
__global__ void __launch_bounds__(128) k1_conv_bn_relu(
    const float* __restrict__ x,  const float* __restrict__ w1,
    const float* __restrict__ b1, const float* __restrict__ gamma,
    const float* __restrict__ beta, const float* __restrict__ mean,
    const float* __restrict__ var)
{
    __shared__ float w1s[16 * 260];          // [cr][c], pitch 260
    const int tid = threadIdx.x;
    const int cr0 = blockIdx.y * 16;

    for (int idx = tid; idx < 16 * C; idx += 128) {
        int i = idx >> 8;
        int c = idx & 255;
        w1s[i * 260 + c] = w1[(cr0 + i) * C + c];
    }
    __syncthreads();

    const int p  = blockIdx.x * 128 + tid;
    const int b  = p / HW;
    const int hw = p - b * HW;
    const float* xb = x + (size_t)b * C * HW + hw;

    float acc[16];
#pragma unroll
    for (int i = 0; i < 16; i++) acc[i] = 0.f;

    for (int c = 0; c < C; c += 4) {
        float xv0 = xb[c * HW];
        float xv1 = xb[(c + 1) * HW];
        float xv2 = xb[(c + 2) * HW];
        float xv3 = xb[(c + 3) * HW];
#pragma unroll
        for (int i = 0; i < 16; i++) {
            float4 w = *(const float4*)&w1s[i * 260 + c];
            acc[i] += w.x * xv0 + w.y * xv1 + w.z * xv2 + w.w * xv3;
        }
    }

#pragma unroll
    for (int i = 0; i < 16; i++) {
        int cr = cr0 + i;
        float inv   = gamma[cr] * rsqrtf(var[cr] + 1e-5f);
        float shift = beta[cr] - mean[cr] * inv;
        acc[i] = fmaxf((acc[i] + b1[cr]) * inv + shift, 0.f);
    }
    uint32_t pk[8];
#pragma unroll
    for (int i = 0; i < 8; i++) {
        __half2 h = __floats2half2_rn(acc[2 * i], acc[2 * i + 1]);
        pk[i] = *(uint32_t*)&h;
    }
    uint4* dst = (uint4*)(g_yh + (size_t)(b * HW + hw) * Cr + cr0);
    dst[0] = make_uint4(pk[0], pk[1], pk[2], pk[3]);
    dst[1] = make_uint4(pk[4], pk[5], pk[6], pk[7]);
}

// ---------------------------------------------------------------------------
// k2: block = (row strip, batch, group). grid (7, 4, 64), 128 thr, 4 CTAs/SM.
// smem (50432B):
//   A(w2 fp16)@0      64 rows x 144B              = 9216
//   B(y fp16)@9216    2 x 64 rows x 144B          = 18432  -> 27648
//   wts16@27648       2 x [50][72]half buffers    = 14336  -> 41984
//   xs16@41984        4ch x 14 x 72 half          = 8064   -> 50176(pad)
//   b2s@50176         [49]f32                     -> 50432
// ---------------------------------------------------------------------------
#define S_A   0u
#define S_B   9216u
#define S_WTS 27648u
#define S_XS  41984u
#define S_B2  50176u
#define SMEM_K2 50432

__global__ void __launch_bounds__(128, 4) k2_involution(
    const float* __restrict__ x,  const float* __restrict__ w2,
    const float* __restrict__ b2, float* __restrict__ out)
{
    extern __shared__ __align__(16) char buf[];
    const uint32_t sb = smem_u32(buf);
    const int tid = threadIdx.x, wid = tid >> 5, lane = tid & 31;
    const int nq = wid;                  // GEMM: warp owns px [16nq, 16nq+16)
    const int b  = blockIdx.y;
    const int g  = blockIdx.z;
    const int h0 = blockIdx.x * 8;

    __half* xs16 = (__half*)(buf + S_XS);
    float*  b2s  = (float*)(buf + S_B2);

    // ---- stage A: w2 fp32 -> fp16 (49 rows x 64, pitch 144B) ----
    for (int idx = tid; idx < K2 * 8; idx += 128) {
        int r = idx >> 3, j = idx & 7;
        const float4* src = (const float4*)(w2 + (size_t)(g * K2 + r) * Cr + j * 8);
        float4 v0 = src[0], v1 = src[1];
        __half2 h0h = __floats2half2_rn(v0.x, v0.y);
        __half2 h1h = __floats2half2_rn(v0.z, v0.w);
        __half2 h2h = __floats2half2_rn(v1.x, v1.y);
        __half2 h3h = __floats2half2_rn(v1.z, v1.w);
        uint4 pk;
        pk.x = *(uint32_t*)&h0h; pk.y = *(uint32_t*)&h1h;
        pk.z = *(uint32_t*)&h2h; pk.w = *(uint32_t*)&h3h;
        *(uint4*)(buf + S_A + (uint32_t)(r * 144 + j * 16)) = pk;
    }
    // zero-pad A rows 49..63
    for (int idx = tid; idx < 15 * 9; idx += 128) {
        int r = 49 + idx / 9, j = idx % 9;
        *(uint4*)(buf + S_A + (uint32_t)(r * 144 + j * 16)) = make_uint4(0, 0, 0, 0);
    }
    if (tid < K2) b2s[tid] = b2[g * K2 + tid];
    // ---- stage x halo strip -> fp16: 4 ch x 14 rows x 62 cols (pitch 72) ----
    for (int idx = tid; idx < 4 * 14 * 62; idx += 128) {
        int ch = idx / 868, rem = idx - ch * 868;
        int r = rem / 62, col = rem - r * 62;
        int hh = h0 + r - 3, ww = col - 3;
        float v = 0.f;
        if (hh >= 0 && hh < Hdim && ww >= 0 && ww < Hdim)
            v = x[((size_t)(b * C + g * 4 + ch) * Hdim + hh) * Hdim + ww];
        xs16[(ch * 14 + r) * 72 + col] = __float2half(v);
    }

    // ---- cp.async y stager: 64 px rows x 8 x 16B = 512 ops ----
    const char* yhp = (const char*)g_yh;
    auto stage_B = [&](int tw, int q) {
#pragma unroll
        for (int it = 0; it < 4; it++) {
            int idx = it * 128 + tid;
            int n = idx >> 3, j = idx & 7;
            int hw = (h0 + (n >> 3)) * Hdim + tw * 8 + (n & 7);
            uint32_t dst = sb + S_B + (uint32_t)(q * 9216 + n * 144 + j * 16);
            CP_ASYNC16(dst, yhp + (size_t)(b * HW + hw) * 128 + j * 16);
        }
    };

    stage_B(0, 0);
    CP_COMMIT();
    __syncthreads();    // A + xs16 + b2s visible

    // ---- ldmatrix A fragments (4 m-tiles, persist across chunks) ----
    uint32_t ah[4][4][4];
    const uint32_t aoff = ((uint32_t)(lane & 15) * 72 + (uint32_t)(lane >> 4) * 8) * 2;
#pragma unroll
    for (int mt = 0; mt < 4; mt++) {
        uint32_t rowb = (uint32_t)(mt * 16 * 144);
#pragma unroll
        for (int kk = 0; kk < 4; kk++)
            LDSM_X4(ah[mt][kk][0], ah[mt][kk][1], ah[mt][kk][2], ah[mt][kk][3],
                    sb + S_A + aoff + rowb + (uint32_t)(kk * 32));
    }

    const uint32_t boff = ((uint32_t)(nq * 16 + (lane & 7)) * 72
                         + (uint32_t)((lane >> 3) & 1) * 8) * 2;

    // involution mapping: thread = (px-pair, channel); warp = channel
    const int pp  = tid & 31;            // px-pair -> px0 = 2*pp (in tile)
    const int chw = tid >> 5;            // 0..3 channel in group
    const int phi = pp >> 2;             // output row 0..7
    const int pwi = (pp & 3) * 2;        // even output col 0,2,4,6

    for (int tw = 0; tw < 7; tw++) {
        const int q  = tw & 1;
        const int w0 = tw * 8;

        if (tw < 6) {
            stage_B(tw + 1, q ^ 1);
            CP_COMMIT();
            CP_WAIT(1);
        } else {
            CP_WAIT(0);
        }
        __syncthreads();   // B(tw) visible to all threads

        // ---- GEMM: single-pass fp16, A persistent in registers ----
        const uint32_t bhi = sb + S_B + (uint32_t)(q * 9216);
        float c[4][2][4];
#pragma unroll
        for (int mt = 0; mt < 4; mt++)
#pragma unroll
            for (int nt = 0; nt < 2; nt++)
#pragma unroll
                for (int i = 0; i < 4; i++) c[mt][nt][i] = 0.f;

#pragma unroll
        for (int kk = 0; kk < 4; kk++) {
            uint32_t bh[2][2];
#pragma unroll
            for (int nt = 0; nt < 2; nt++) {
                uint32_t o = boff + (uint32_t)(nt * 8 * 144 + kk * 32);
                LDSM_X2(bh[nt][0], bh[nt][1], bhi + o);
            }
#pragma unroll
            for (int mt = 0; mt < 4; mt++)
#pragma unroll
                for (int nt = 0; nt < 2; nt++)
                    MMA16816(c[mt][nt], ah[mt][kk], bh[nt]);
        }

        // ---- epilogue: (c+bias) -> half2 -> wts16[q] (double-buffered) ----
        __half* wtsq = (__half*)(buf + S_WTS + (uint32_t)(q * 7168));
#pragma unroll
        for (int mt = 0; mt < 4; mt++) {
            int r0 = mt * 16 + (lane >> 2);
            int r1 = r0 + 8;
#pragma unroll
            for (int nt = 0; nt < 2; nt++) {
                int col = nq * 16 + nt * 8 + (lane & 3) * 2;
                if (r0 < K2) {
                    float bias = b2s[r0];
                    __half2 h = __floats2half2_rn(c[mt][nt][0] + bias,
                                                  c[mt][nt][1] + bias);
                    *(__half2*)(wtsq + r0 * 72 + col) = h;
                }
                if (r1 < K2) {
                    float bias = b2s[r1];
                    __half2 h = __floats2half2_rn(c[mt][nt][2] + bias,
                                                  c[mt][nt][3] + bias);
                    *(__half2*)(wtsq + r1 * 72 + col) = h;
                }
            }
        }
        __syncthreads();   // wts16[q] visible; xs16 stable

        // ---- involution: px-pair, shared x window (8 halves), half2 wts ----
        float s0 = 0.f, s1 = 0.f;
#pragma unroll
        for (int ky = 0; ky < 7; ky++) {
            const __half2* xrow = (const __half2*)(xs16
                + (chw * 14 + phi + ky) * 72 + w0 + pwi);
            float f[8];
#pragma unroll
            for (int j = 0; j < 4; j++) {
                float2 t = __half22float2(xrow[j]);
                f[2 * j] = t.x; f[2 * j + 1] = t.y;
            }
            const __half2* wrow = (const __half2*)(wtsq + (ky * 7) * 72) + pp;
#pragma unroll
            for (int kx = 0; kx < 7; kx++) {
                float2 w = __half22float2(wrow[kx * 36]);
                s0 += w.x * f[kx];
                s1 += w.y * f[kx + 1];
            }
        }
        // output cols (w0+pwi, w0+pwi+1) at row h0+phi   [R10 bug was 2*pwi]
        *(float2*)(out + ((size_t)(b * C + g * 4 + chw) * Hdim + h0 + phi) * Hdim
                   + w0 + pwi) = make_float2(s0, s1);
    }
}

extern "C" void kernel_launch(void* const* d_in, const int* in_sizes, int n_in,
                              void* d_out, int out_size)
{
    const float* x     = (const float*)d_in[0];
    const float* w1    = (const float*)d_in[1];
    const float* b1    = (const float*)d_in[2];
    const float* gamma = (const float*)d_in[3];
    const float* beta  = (const float*)d_in[4];
    const float* mean  = (const float*)d_in[5];
    const float* var   = (const float*)d_in[6];
    const float* w2    = (const float*)d_in[7];
    const float* b2    = (const float*)d_in[8];
    float* out = (float*)d_out;

    cudaFuncSetAttribute(k2_involution,
                         cudaFuncAttributeMaxDynamicSharedMemorySize, SMEM_K2);

    dim3 g1(98, 4);
    k1_conv_bn_relu<<<g1, 128>>>(x, w1, b1, gamma, beta, mean, var);

    dim3 g2(7, 4, 64);
    k2_involution<<<g2, 128, SMEM_K2>>>(x, w2, b2, out);
}